// round 10
// baseline (speedup 1.0000x reference)
#include <cuda_runtime.h>
#include <cuda_bf16.h>

// MeanAggregator: out[r,:] = mean over UNIQUE neighbors c of row r of embed[c,:]
// row_idx sorted ascending. D = 300 floats = 75 float4.
// Design: one warp per (row, slot); slot s covers float4 indices s*32+lane.
// GATHER-ALL + SUBTRACT-DUPLICATES (dup detect deferred past gather).
// R10: no prefetch (R9 regressed); __launch_bounds__(256,8) caps regs at 32 to
// hit 64-warp/SM occupancy; gather is unroll-4 with two accumulator chains.

#define AGG_D4   75
#define AGG_MAXL 96            // fast-path cap: 3 chunks (L ~ Poisson(32), max ~70)
#define AGG_MAXB 65536
#define WARPS_PB 8             // 256-thread blocks

__device__ int g_row_start[AGG_MAXB + 1];

// CSR row pointers by diff-scatter over the sorted row_idx (O(E), contiguous loads).
__global__ void build_row_starts(const int* __restrict__ row_idx, int E, int B) {
    int i = blockIdx.x * blockDim.x + threadIdx.x;
    if (i > E) return;
    if (i == 0) {
        int cur = row_idx[0];
        for (int v = 0; v <= cur; ++v) g_row_start[v] = 0;
    } else if (i == E) {
        int prev = row_idx[E - 1];
        for (int v = prev + 1; v <= B; ++v) g_row_start[v] = E;
    } else {
        int prev = row_idx[i - 1];
        int cur  = row_idx[i];
        for (int v = prev + 1; v <= cur; ++v) g_row_start[v] = i;
    }
}

__global__ __launch_bounds__(WARPS_PB * 32, 8) void mean_agg_kernel(
    const int*    __restrict__ col_idx,
    const float4* __restrict__ embed4,   // [U, 75]
    float4*       __restrict__ out4,     // [B, 75]
    int B)
{
    const int w    = threadIdx.x >> 5;
    const int lane = threadIdx.x & 31;
    const int gw   = blockIdx.x * WARPS_PB + w;   // global warp id
    const int r    = gw / 3;                      // row
    const int slot = gw - r * 3;                  // LDG slot 0/1/2
    if (r >= B) return;                           // warp-uniform

    const int  d4  = slot * 32 + lane;            // my float4 index in [0,75)
    const bool act = (d4 < AGG_D4);               // slot 2: lanes 0..10 only

    const int start = g_row_start[r];
    const int L     = g_row_start[r + 1] - start;

    __shared__ int s_col[WARPS_PB][AGG_MAXL];
    int* sc = s_col[w];

    float4 a0 = make_float4(0.f, 0.f, 0.f, 0.f);
    float4 a1 = a0;
    const unsigned lt = (1u << lane) - 1u;
    const float4* __restrict__ e = embed4 + d4;
    int Lu = 0;

    if (L <= AGG_MAXL) {
        // ---- 3 independent coalesced chunk loads of col indices ----
        const int j1 = 32 + lane, j2 = 64 + lane;
        int c0 = (lane < L) ? col_idx[start + lane] : -(lane + 1);
        int c1 = (j1   < L) ? col_idx[start + j1]   : -(lane + 1);
        int c2 = (j2   < L) ? col_idx[start + j2]   : -(lane + 1);
        sc[lane] = c0;
        if (j1 < L) sc[j1] = c1;
        if (j2 < L) sc[j2] = c2;
        __syncwarp();

        // ---- main gather over ALL L entries (dups included): unroll-4,
        //      two accumulator chains, 4 independent LDG.128 in flight ----
        if (act) {
            int j = 0;
            for (; j + 4 <= L; j += 4) {
                float4 v0 = e[(size_t)sc[j]     * AGG_D4];
                float4 v1 = e[(size_t)sc[j + 1] * AGG_D4];
                float4 v2 = e[(size_t)sc[j + 2] * AGG_D4];
                float4 v3 = e[(size_t)sc[j + 3] * AGG_D4];
                a0.x += v0.x + v2.x; a0.y += v0.y + v2.y;
                a0.z += v0.z + v2.z; a0.w += v0.w + v2.w;
                a1.x += v1.x + v3.x; a1.y += v1.y + v3.y;
                a1.z += v1.z + v3.z; a1.w += v1.w + v3.w;
            }
            for (; j < L; ++j) {
                float4 v = e[(size_t)sc[j] * AGG_D4];
                a0.x += v.x; a0.y += v.y; a0.z += v.z; a0.w += v.w;
            }
        }

        // ---- duplicate detection AFTER the gather (all lanes participate) ----
        unsigned p0m = __match_any_sync(0xffffffffu, c0);
        bool d0 = (lane < L) && ((p0m & lt) != 0);
        bool d1 = false, d2 = false;
        if (L > 32) {
            unsigned p1m = __match_any_sync(0xffffffffu, c1);
            d1 = (j1 < L) && ((p1m & lt) != 0);
            if (!d1 && j1 < L) {
                for (int i = 0; i < 32; ++i)
                    if (sc[i] == c1) { d1 = true; break; }
            }
            if (L > 64) {
                unsigned p2m = __match_any_sync(0xffffffffu, c2);
                d2 = (j2 < L) && ((p2m & lt) != 0);
                if (!d2 && j2 < L) {
                    for (int i = 0; i < 64; ++i)
                        if (sc[i] == c2) { d2 = true; break; }
                }
            }
        }
        const unsigned m0 = __ballot_sync(0xffffffffu, d0);
        const unsigned m1 = __ballot_sync(0xffffffffu, d1);
        const unsigned m2 = __ballot_sync(0xffffffffu, d2);
        Lu = L - (__popc(m0) + __popc(m1) + __popc(m2));

        // ---- subtract duplicate occurrences (almost always all-zero masks) ----
        if (act && (m0 | m1 | m2)) {
            unsigned masks[3] = { m0, m1, m2 };
            #pragma unroll
            for (int k = 0; k < 3; ++k) {
                unsigned m = masks[k];
                while (m) {
                    int b = __ffs(m) - 1; m &= m - 1;
                    float4 v = e[(size_t)sc[k * 32 + b] * AGG_D4];
                    a0.x -= v.x; a0.y -= v.y; a0.z -= v.z; a0.w -= v.w;
                }
            }
        }
    } else {
        // Unreachable-for-this-data fallback: O(L^2) global dedup, direct accumulate.
        for (int j = 0; j < L; ++j) {
            int c = col_idx[start + j];
            bool valid = true;
            for (int i = 0; i < j; ++i)
                if (col_idx[start + i] == c) { valid = false; break; }
            if (!valid) continue;
            ++Lu;
            if (act) {
                float4 v = e[(size_t)c * AGG_D4];
                a0.x += v.x; a0.y += v.y; a0.z += v.z; a0.w += v.w;
            }
        }
    }

    if (act) {
        const float inv = 1.0f / fmaxf((float)Lu, 1e-8f);
        float4 t;
        t.x = (a0.x + a1.x) * inv;
        t.y = (a0.y + a1.y) * inv;
        t.z = (a0.z + a1.z) * inv;
        t.w = (a0.w + a1.w) * inv;
        out4[(size_t)r * AGG_D4 + d4] = t;
    }
}

extern "C" void kernel_launch(void* const* d_in, const int* in_sizes, int n_in,
                              void* d_out, int out_size) {
    const int*   row_idx = (const int*)  d_in[0];
    const int*   col_idx = (const int*)  d_in[1];
    const float* embed   = (const float*)d_in[2];
    float*       out     = (float*)      d_out;

    const int E = in_sizes[0];
    const int B = out_size / 300;

    const int total_warps = 3 * B;
    build_row_starts<<<(E + 1 + 255) / 256, 256>>>(row_idx, E, B);
    mean_agg_kernel<<<(total_warps + WARPS_PB - 1) / WARPS_PB, WARPS_PB * 32>>>(
        col_idx, (const float4*)embed, (float4*)out, B);
}

// round 11
// speedup vs baseline: 1.0838x; 1.0838x over previous
#include <cuda_runtime.h>
#include <cuda_bf16.h>

// MeanAggregator: out[r,:] = mean over UNIQUE neighbors c of row r of embed[c,:]
// row_idx sorted ascending. D = 300 floats = 75 float4.
// Design: one warp per (row, slot, parity). slot s covers float4 indices
// s*32+lane (identical coalescing to R8); parity p gathers neighbors j with
// j%2==p (halves the per-warp serial batch chain). GATHER-ALL + SUBTRACT-
// DUPLICATES, dup detect deferred past the gather. The two parity warps of a
// (row,slot) pair combine through smem with a pair-local named barrier
// (bar.sync id,64) -- no block-wide coupling. Deterministic everywhere.

#define AGG_D4   75
#define AGG_MAXL 96            // fast-path cap (L ~ Poisson(32), max ~70)
#define AGG_MAXB 65536
#define PAIRS_PB 4             // (row,slot) pairs per 256-thread block

__device__ int g_row_start[AGG_MAXB + 1];

// CSR row pointers by diff-scatter over the sorted row_idx (O(E), contiguous loads).
__global__ void build_row_starts(const int* __restrict__ row_idx, int E, int B) {
    int i = blockIdx.x * blockDim.x + threadIdx.x;
    if (i > E) return;
    if (i == 0) {
        int cur = row_idx[0];
        for (int v = 0; v <= cur; ++v) g_row_start[v] = 0;
    } else if (i == E) {
        int prev = row_idx[E - 1];
        for (int v = prev + 1; v <= B; ++v) g_row_start[v] = E;
    } else {
        int prev = row_idx[i - 1];
        int cur  = row_idx[i];
        for (int v = prev + 1; v <= cur; ++v) g_row_start[v] = i;
    }
}

__global__ __launch_bounds__(PAIRS_PB * 64) void mean_agg_kernel(
    const int*    __restrict__ col_idx,
    const float4* __restrict__ embed4,   // [U, 75]
    float4*       __restrict__ out4,     // [B, 75]
    int B)
{
    const int w      = threadIdx.x >> 5;         // 0..7
    const int lane   = threadIdx.x & 31;
    const int pairL  = w >> 1;                   // pair slot in block (0..3)
    const int parity = w & 1;
    const int gp     = blockIdx.x * PAIRS_PB + pairL;   // global (row,slot) pair
    const int r      = gp / 3;
    const int slot   = gp - r * 3;
    if (r >= B) return;                          // warp-uniform (both warps of pair)

    const int  d4  = slot * 32 + lane;           // my float4 index in [0,75)
    const bool act = (d4 < AGG_D4);              // slot 2: lanes 0..10 only

    const int start = g_row_start[r];
    const int L     = g_row_start[r + 1] - start;

    __shared__ int    s_col[PAIRS_PB * 2][AGG_MAXL];
    __shared__ float4 s_part[PAIRS_PB][32];      // parity-1 partials
    int* sc = s_col[w];

    float4 a0 = make_float4(0.f, 0.f, 0.f, 0.f);
    float4 a1 = a0;
    const unsigned lt = (1u << lane) - 1u;
    const float4* __restrict__ e = embed4 + d4;
    int Lu = 0;

    if (L <= AGG_MAXL) {
        // ---- 3 independent coalesced chunk loads of col indices ----
        const int j1 = 32 + lane, j2 = 64 + lane;
        int c0 = (lane < L) ? col_idx[start + lane] : -(lane + 1);
        int c1 = (j1   < L) ? col_idx[start + j1]   : -(lane + 1);
        int c2 = (j2   < L) ? col_idx[start + j2]   : -(lane + 1);
        sc[lane] = c0;
        if (j1 < L) sc[j1] = c1;
        if (j2 < L) sc[j2] = c2;
        __syncwarp();

        // ---- gather own parity half (j = parity, parity+2, ...): unroll-8 ----
        if (act) {
            int j = parity;
            for (; j + 14 < L; j += 16) {
                float4 v0 = e[(size_t)sc[j]      * AGG_D4];
                float4 v1 = e[(size_t)sc[j + 2]  * AGG_D4];
                float4 v2 = e[(size_t)sc[j + 4]  * AGG_D4];
                float4 v3 = e[(size_t)sc[j + 6]  * AGG_D4];
                float4 v4 = e[(size_t)sc[j + 8]  * AGG_D4];
                float4 v5 = e[(size_t)sc[j + 10] * AGG_D4];
                float4 v6 = e[(size_t)sc[j + 12] * AGG_D4];
                float4 v7 = e[(size_t)sc[j + 14] * AGG_D4];
                a0.x += (v0.x + v1.x) + (v2.x + v3.x);
                a0.y += (v0.y + v1.y) + (v2.y + v3.y);
                a0.z += (v0.z + v1.z) + (v2.z + v3.z);
                a0.w += (v0.w + v1.w) + (v2.w + v3.w);
                a1.x += (v4.x + v5.x) + (v6.x + v7.x);
                a1.y += (v4.y + v5.y) + (v6.y + v7.y);
                a1.z += (v4.z + v5.z) + (v6.z + v7.z);
                a1.w += (v4.w + v5.w) + (v6.w + v7.w);
            }
            for (; j < L; j += 2) {
                float4 v = e[(size_t)sc[j] * AGG_D4];
                a0.x += v.x; a0.y += v.y; a0.z += v.z; a0.w += v.w;
            }
        }

        // ---- duplicate detection AFTER the gather (identical in both warps) ----
        unsigned p0m = __match_any_sync(0xffffffffu, c0);
        bool d0 = (lane < L) && ((p0m & lt) != 0);
        bool d1 = false, d2 = false;
        if (L > 32) {
            unsigned p1m = __match_any_sync(0xffffffffu, c1);
            d1 = (j1 < L) && ((p1m & lt) != 0);
            if (!d1 && j1 < L) {
                for (int i = 0; i < 32; ++i)
                    if (sc[i] == c1) { d1 = true; break; }
            }
            if (L > 64) {
                unsigned p2m = __match_any_sync(0xffffffffu, c2);
                d2 = (j2 < L) && ((p2m & lt) != 0);
                if (!d2 && j2 < L) {
                    for (int i = 0; i < 64; ++i)
                        if (sc[i] == c2) { d2 = true; break; }
                }
            }
        }
        const unsigned m0 = __ballot_sync(0xffffffffu, d0);
        const unsigned m1 = __ballot_sync(0xffffffffu, d1);
        const unsigned m2 = __ballot_sync(0xffffffffu, d2);
        Lu = L - (__popc(m0) + __popc(m1) + __popc(m2));

        // ---- subtract own-parity duplicate occurrences ----
        // position k*32+b has parity (b&1) since k*32 is even.
        const unsigned psel = parity ? 0xAAAAAAAAu : 0x55555555u;
        const unsigned n0 = m0 & psel, n1 = m1 & psel, n2 = m2 & psel;
        if (act && (n0 | n1 | n2)) {
            unsigned masks[3] = { n0, n1, n2 };
            #pragma unroll
            for (int k = 0; k < 3; ++k) {
                unsigned m = masks[k];
                while (m) {
                    int b = __ffs(m) - 1; m &= m - 1;
                    float4 v = e[(size_t)sc[k * 32 + b] * AGG_D4];
                    a0.x -= v.x; a0.y -= v.y; a0.z -= v.z; a0.w -= v.w;
                }
            }
        }
    } else {
        // Unreachable-for-this-data fallback: O(L^2) global dedup; unique
        // ordinals split by parity. Both warps compute the same Lu.
        int seen = 0;
        for (int j = 0; j < L; ++j) {
            int c = col_idx[start + j];
            bool valid = true;
            for (int i = 0; i < j; ++i)
                if (col_idx[start + i] == c) { valid = false; break; }
            if (!valid) continue;
            int my = seen++;
            if ((my & 1) != parity) continue;
            if (act) {
                float4 v = e[(size_t)c * AGG_D4];
                a0.x += v.x; a0.y += v.y; a0.z += v.z; a0.w += v.w;
            }
        }
        Lu = seen;
    }

    // ---- pair-local combine: parity 1 -> smem, named barrier (64 thr), parity 0 writes ----
    float4 mine;
    mine.x = a0.x + a1.x; mine.y = a0.y + a1.y;
    mine.z = a0.z + a1.z; mine.w = a0.w + a1.w;

    if (parity == 1 && act) s_part[pairL][lane] = mine;
    {
        const int bid = 1 + pairL;               // named barriers 1..4
        asm volatile("bar.sync %0, %1;" :: "r"(bid), "r"(64) : "memory");
    }
    if (parity == 0 && act) {
        const float inv = 1.0f / fmaxf((float)Lu, 1e-8f);
        float4 o = s_part[pairL][lane];
        float4 t;
        t.x = (mine.x + o.x) * inv;
        t.y = (mine.y + o.y) * inv;
        t.z = (mine.z + o.z) * inv;
        t.w = (mine.w + o.w) * inv;
        __stcs(&out4[(size_t)r * AGG_D4 + d4], t);
    }
}

extern "C" void kernel_launch(void* const* d_in, const int* in_sizes, int n_in,
                              void* d_out, int out_size) {
    const int*   row_idx = (const int*)  d_in[0];
    const int*   col_idx = (const int*)  d_in[1];
    const float* embed   = (const float*)d_in[2];
    float*       out     = (float*)      d_out;

    const int E = in_sizes[0];
    const int B = out_size / 300;

    const int total_pairs = 3 * B;
    build_row_starts<<<(E + 1 + 255) / 256, 256>>>(row_idx, E, B);
    mean_agg_kernel<<<(total_pairs + PAIRS_PB - 1) / PAIRS_PB, PAIRS_PB * 64>>>(
        col_idx, (const float4*)embed, (float4*)out, B);
}

// round 12
// speedup vs baseline: 1.1606x; 1.0708x over previous
#include <cuda_runtime.h>
#include <cuda_bf16.h>

// MeanAggregator: out[r,:] = mean over UNIQUE neighbors c of row r of embed[c,:]
// row_idx sorted ascending. D = 300 floats = 75 float4.
// R12 pipeline:
//   K1 build_row_starts: CSR pointers via diff-scatter.
//   K2 dedup_rows: per-row warp dedup ONCE -> compacted unique list g_cols
//      (zero-padded to multiple of 8) + count g_cnt.
//   K3 gather (hot): warp-per-(row,slot). Prologue = 4 independent loads at
//      addresses known from r alone; branch-free unroll-8 gather over padded
//      list; subtract npad * embed[0] correction. No dedup in hot kernel.

#define AGG_D4   75
#define AGG_MAXU 96            // padded unique-list stride (L ~ Poisson(32), max ~70)
#define AGG_MAXB 65536
#define WARPS_PB 8             // 256-thread blocks

__device__ int g_row_start[AGG_MAXB + 1];
__device__ int g_cnt[AGG_MAXB];
__device__ int g_cols[(size_t)AGG_MAXB * AGG_MAXU];

// K1: CSR row pointers by diff-scatter over sorted row_idx (O(E), contiguous).
__global__ void build_row_starts(const int* __restrict__ row_idx, int E, int B) {
    int i = blockIdx.x * blockDim.x + threadIdx.x;
    if (i > E) return;
    if (i == 0) {
        int cur = row_idx[0];
        for (int v = 0; v <= cur; ++v) g_row_start[v] = 0;
    } else if (i == E) {
        int prev = row_idx[E - 1];
        for (int v = prev + 1; v <= B; ++v) g_row_start[v] = E;
    } else {
        int prev = row_idx[i - 1];
        int cur  = row_idx[i];
        for (int v = prev + 1; v <= cur; ++v) g_row_start[v] = i;
    }
}

// K2: warp-per-row dedup + order-preserving compaction into g_cols.
__global__ __launch_bounds__(WARPS_PB * 32) void dedup_rows(
    const int* __restrict__ col_idx, int B)
{
    const int w    = threadIdx.x >> 5;
    const int lane = threadIdx.x & 31;
    const int r    = blockIdx.x * WARPS_PB + w;
    if (r >= B) return;

    const int start = g_row_start[r];
    const int L     = g_row_start[r + 1] - start;
    int* dst = g_cols + (size_t)r * AGG_MAXU;
    const unsigned lt = (1u << lane) - 1u;

    if (L <= AGG_MAXU) {
        __shared__ int s_col[WARPS_PB][AGG_MAXU];
        int* sc = s_col[w];
        const int j1 = 32 + lane, j2 = 64 + lane;
        int c0 = (lane < L) ? col_idx[start + lane] : -(lane + 1);
        int c1 = (j1   < L) ? col_idx[start + j1]   : -(lane + 1);
        int c2 = (j2   < L) ? col_idx[start + j2]   : -(lane + 1);
        sc[lane] = c0;
        if (j1 < L) sc[j1] = c1;
        if (j2 < L) sc[j2] = c2;
        __syncwarp();

        // chunk 0
        unsigned p0 = __match_any_sync(0xffffffffu, c0);
        bool v0 = (lane < L) && ((p0 & lt) == 0);
        unsigned m0 = __ballot_sync(0xffffffffu, v0);
        if (v0) dst[__popc(m0 & lt)] = c0;
        int base = __popc(m0);
        // chunk 1
        if (L > 32) {
            unsigned p1 = __match_any_sync(0xffffffffu, c1);
            bool v1 = (j1 < L) && ((p1 & lt) == 0);
            if (v1) { for (int i = 0; i < 32; ++i) if (sc[i] == c1) { v1 = false; break; } }
            unsigned m1 = __ballot_sync(0xffffffffu, v1);
            if (v1) dst[base + __popc(m1 & lt)] = c1;
            base += __popc(m1);
            // chunk 2
            if (L > 64) {
                unsigned p2 = __match_any_sync(0xffffffffu, c2);
                bool v2 = (j2 < L) && ((p2 & lt) == 0);
                if (v2) { for (int i = 0; i < 64; ++i) if (sc[i] == c2) { v2 = false; break; } }
                unsigned m2 = __ballot_sync(0xffffffffu, v2);
                if (v2) dst[base + __popc(m2 & lt)] = c2;
                base += __popc(m2);
            }
        }
        // zero-pad to multiple of 8 (index 0 -> corrected in K3)
        const int cnt8 = (base + 7) & ~7;
        if (lane < cnt8 - base) dst[base + lane] = 0;
        if (lane == 0) g_cnt[r] = base;
    } else {
        if (lane == 0) g_cnt[r] = -L;   // unreachable-for-this-data fallback flag
    }
}

// K3 (hot): warp per (row, slot); slot s covers float4 indices s*32+lane.
__global__ __launch_bounds__(WARPS_PB * 32) void gather_kernel(
    const int*    __restrict__ col_idx,
    const float4* __restrict__ embed4,   // [U, 75]
    float4*       __restrict__ out4,     // [B, 75]
    int B)
{
    const int w    = threadIdx.x >> 5;
    const int lane = threadIdx.x & 31;
    const int gw   = blockIdx.x * WARPS_PB + w;
    const int r    = gw / 3;
    const int slot = gw - r * 3;
    if (r >= B) return;                       // warp-uniform

    const int  d4  = slot * 32 + lane;
    const bool act = (d4 < AGG_D4);           // slot 2: lanes 0..10

    // All four prologue loads are independent, addresses known from r alone.
    const int cnt = g_cnt[r];
    const int* __restrict__ src = g_cols + (size_t)r * AGG_MAXU;

    __shared__ int s_col[WARPS_PB][AGG_MAXU];
    int* sc = s_col[w];

    float4 a0 = make_float4(0.f, 0.f, 0.f, 0.f);
    float4 a1 = a0;
    const float4* __restrict__ e = embed4 + d4;
    int Lu;

    if (cnt >= 0) {
        sc[lane]      = src[lane];
        sc[32 + lane] = src[32 + lane];
        sc[64 + lane] = src[64 + lane];
        __syncwarp();
        Lu = cnt;

        if (act) {
            const int cnt8 = (cnt + 7) & ~7;
            // branch-free unroll-8 over the padded list
            for (int j = 0; j < cnt8; j += 8) {
                float4 v0 = e[(size_t)sc[j]     * AGG_D4];
                float4 v1 = e[(size_t)sc[j + 1] * AGG_D4];
                float4 v2 = e[(size_t)sc[j + 2] * AGG_D4];
                float4 v3 = e[(size_t)sc[j + 3] * AGG_D4];
                float4 v4 = e[(size_t)sc[j + 4] * AGG_D4];
                float4 v5 = e[(size_t)sc[j + 5] * AGG_D4];
                float4 v6 = e[(size_t)sc[j + 6] * AGG_D4];
                float4 v7 = e[(size_t)sc[j + 7] * AGG_D4];
                a0.x += (v0.x + v1.x) + (v2.x + v3.x);
                a0.y += (v0.y + v1.y) + (v2.y + v3.y);
                a0.z += (v0.z + v1.z) + (v2.z + v3.z);
                a0.w += (v0.w + v1.w) + (v2.w + v3.w);
                a1.x += (v4.x + v5.x) + (v6.x + v7.x);
                a1.y += (v4.y + v5.y) + (v6.y + v7.y);
                a1.z += (v4.z + v5.z) + (v6.z + v7.z);
                a1.w += (v4.w + v5.w) + (v6.w + v7.w);
            }
            // remove the npad copies of embed row 0 added by the padding
            const int npad = cnt8 - cnt;
            if (npad) {
                float4 z = e[0];               // embed row 0, L2-hot
                const float f = (float)npad;
                a0.x -= f * z.x; a0.y -= f * z.y;
                a0.z -= f * z.z; a0.w -= f * z.w;
            }
        }
    } else {
        // Unreachable-for-this-data fallback: O(L^2) dedup straight from col_idx.
        const int start = g_row_start[r];
        const int L     = -cnt;
        int seen = 0;
        for (int j = 0; j < L; ++j) {
            int c = col_idx[start + j];
            bool valid = true;
            for (int i = 0; i < j; ++i)
                if (col_idx[start + i] == c) { valid = false; break; }
            if (!valid) continue;
            ++seen;
            if (act) {
                float4 v = e[(size_t)c * AGG_D4];
                a0.x += v.x; a0.y += v.y; a0.z += v.z; a0.w += v.w;
            }
        }
        Lu = seen;
    }

    if (act) {
        const float inv = 1.0f / fmaxf((float)Lu, 1e-8f);
        float4 t;
        t.x = (a0.x + a1.x) * inv;
        t.y = (a0.y + a1.y) * inv;
        t.z = (a0.z + a1.z) * inv;
        t.w = (a0.w + a1.w) * inv;
        __stcs(&out4[(size_t)r * AGG_D4 + d4], t);
    }
}

extern "C" void kernel_launch(void* const* d_in, const int* in_sizes, int n_in,
                              void* d_out, int out_size) {
    const int*   row_idx = (const int*)  d_in[0];
    const int*   col_idx = (const int*)  d_in[1];
    const float* embed   = (const float*)d_in[2];
    float*       out     = (float*)      d_out;

    const int E = in_sizes[0];
    const int B = out_size / 300;

    build_row_starts<<<(E + 1 + 255) / 256, 256>>>(row_idx, E, B);
    dedup_rows<<<(B + WARPS_PB - 1) / WARPS_PB, WARPS_PB * 32>>>(col_idx, B);
    const int total_warps = 3 * B;
    gather_kernel<<<(total_warps + WARPS_PB - 1) / WARPS_PB, WARPS_PB * 32>>>(
        col_idx, (const float4*)embed, (float4*)out, B);
}

// round 14
// speedup vs baseline: 1.3846x; 1.1931x over previous
#include <cuda_runtime.h>
#include <cuda_bf16.h>

// MeanAggregator: out[r,:] = mean over UNIQUE neighbors c of row r of embed[c,:]
// row_idx sorted ascending. D = 300 floats = 75 float4.
// R14 = R8 chassis (warp per (row,slot), GATHER-ALL + SUBTRACT-DUPLICATES,
// dedup deferred past gather) +
//   (a) vectorized int4 CSR build (4 boundaries/thread, shfl for prev), and
//   (b) embed loads via createpolicy L2::evict_last + ld.global.nc.L2::cache_hint
//       (valid on any width, unlike the direct evict_last qualifier) so the
//       60MB table sticks in the 126MB L2 across graph replays.
//       Output uses __stcs to stream past L2.

#define AGG_D4   75
#define AGG_MAXL 96            // fast-path cap: 3 chunks (L ~ Poisson(32), max ~70)
#define AGG_MAXB 65536
#define WARPS_PB 8             // 256-thread blocks

__device__ int g_row_start[AGG_MAXB + 1];

// L2 evict_last policy (fractional 1.0), created once per thread.
__device__ __forceinline__ unsigned long long make_evict_last_policy() {
    unsigned long long pol;
    asm("createpolicy.fractional.L2::evict_last.b64 %0, 1.0;" : "=l"(pol));
    return pol;
}

// L2-sticky vector load for the embedding table (cache_hint form).
__device__ __forceinline__ float4 ldg_el(const float4* __restrict__ p,
                                         unsigned long long pol) {
    float4 v;
    asm("ld.global.nc.L2::cache_hint.v4.f32 {%0,%1,%2,%3}, [%4], %5;"
        : "=f"(v.x), "=f"(v.y), "=f"(v.z), "=f"(v.w) : "l"(p), "l"(pol));
    return v;
}

// K1: CSR row pointers by diff-scatter, vectorized: each thread owns boundaries
// i in [4t, 4t+4). Fast path: one int4 load + shfl_up for row_idx[4t-1]
// (lane 0 patches with a scalar load). Edges fall back to the scalar logic.
__global__ void build_row_starts(const int* __restrict__ row_idx, int E, int B) {
    const int t    = blockIdx.x * blockDim.x + threadIdx.x;
    const int lane = threadIdx.x & 31;
    const int i0   = t * 4;
    if (i0 > E) return;

    if (i0 > 0 && i0 + 4 <= E) {
        int4 q = *reinterpret_cast<const int4*>(row_idx + i0);
        int prevv = __shfl_up_sync(0xffffffffu, q.w, 1);
        if (lane == 0) prevv = row_idx[i0 - 1];
        int vals[4] = { q.x, q.y, q.z, q.w };
        int p = prevv;
        #pragma unroll
        for (int k = 0; k < 4; ++k) {
            int cur = vals[k];
            for (int v = p + 1; v <= cur; ++v) g_row_start[v] = i0 + k;
            p = cur;
        }
    } else {
        // shfl source above may be inactive here; pure scalar edge handling
        #pragma unroll
        for (int k = 0; k < 4; ++k) {
            int i = i0 + k;
            if (i > E) break;
            if (i == 0) {
                int cur = row_idx[0];
                for (int v = 0; v <= cur; ++v) g_row_start[v] = 0;
            } else if (i == E) {
                int prev = row_idx[E - 1];
                for (int v = prev + 1; v <= B; ++v) g_row_start[v] = E;
            } else {
                int prev = row_idx[i - 1];
                int cur  = row_idx[i];
                for (int v = prev + 1; v <= cur; ++v) g_row_start[v] = i;
            }
        }
    }
}

__global__ __launch_bounds__(WARPS_PB * 32) void mean_agg_kernel(
    const int*    __restrict__ col_idx,
    const float4* __restrict__ embed4,   // [U, 75]
    float4*       __restrict__ out4,     // [B, 75]
    int B)
{
    const int w    = threadIdx.x >> 5;
    const int lane = threadIdx.x & 31;
    const int gw   = blockIdx.x * WARPS_PB + w;   // global warp id
    const int r    = gw / 3;                      // row
    const int slot = gw - r * 3;                  // LDG slot 0/1/2
    if (r >= B) return;                           // warp-uniform

    const int  d4  = slot * 32 + lane;            // my float4 index in [0,75)
    const bool act = (d4 < AGG_D4);               // slot 2: lanes 0..10 only

    const int start = g_row_start[r];
    const int L     = g_row_start[r + 1] - start;

    __shared__ int s_col[WARPS_PB][AGG_MAXL];
    int* sc = s_col[w];

    float4 a0 = make_float4(0.f, 0.f, 0.f, 0.f);
    float4 a1 = a0;
    const unsigned lt = (1u << lane) - 1u;
    const float4* __restrict__ e = embed4 + d4;
    const unsigned long long pol = make_evict_last_policy();
    int Lu = 0;

    if (L <= AGG_MAXL) {
        // ---- 3 independent coalesced chunk loads of col indices ----
        const int j1 = 32 + lane, j2 = 64 + lane;
        int c0 = (lane < L) ? col_idx[start + lane] : -(lane + 1);
        int c1 = (j1   < L) ? col_idx[start + j1]   : -(lane + 1);
        int c2 = (j2   < L) ? col_idx[start + j2]   : -(lane + 1);
        sc[lane] = c0;
        if (j1 < L) sc[j1] = c1;
        if (j2 < L) sc[j2] = c2;
        __syncwarp();

        // ---- main gather over ALL L entries (dups included): unroll-8,
        //      L2-sticky loads keep the table resident across replays ----
        if (act) {
            int j = 0;
            for (; j + 8 <= L; j += 8) {
                float4 v0 = ldg_el(e + (size_t)sc[j]     * AGG_D4, pol);
                float4 v1 = ldg_el(e + (size_t)sc[j + 1] * AGG_D4, pol);
                float4 v2 = ldg_el(e + (size_t)sc[j + 2] * AGG_D4, pol);
                float4 v3 = ldg_el(e + (size_t)sc[j + 3] * AGG_D4, pol);
                float4 v4 = ldg_el(e + (size_t)sc[j + 4] * AGG_D4, pol);
                float4 v5 = ldg_el(e + (size_t)sc[j + 5] * AGG_D4, pol);
                float4 v6 = ldg_el(e + (size_t)sc[j + 6] * AGG_D4, pol);
                float4 v7 = ldg_el(e + (size_t)sc[j + 7] * AGG_D4, pol);
                a0.x += (v0.x + v1.x) + (v2.x + v3.x);
                a0.y += (v0.y + v1.y) + (v2.y + v3.y);
                a0.z += (v0.z + v1.z) + (v2.z + v3.z);
                a0.w += (v0.w + v1.w) + (v2.w + v3.w);
                a1.x += (v4.x + v5.x) + (v6.x + v7.x);
                a1.y += (v4.y + v5.y) + (v6.y + v7.y);
                a1.z += (v4.z + v5.z) + (v6.z + v7.z);
                a1.w += (v4.w + v5.w) + (v6.w + v7.w);
            }
            for (; j + 4 <= L; j += 4) {
                float4 v0 = ldg_el(e + (size_t)sc[j]     * AGG_D4, pol);
                float4 v1 = ldg_el(e + (size_t)sc[j + 1] * AGG_D4, pol);
                float4 v2 = ldg_el(e + (size_t)sc[j + 2] * AGG_D4, pol);
                float4 v3 = ldg_el(e + (size_t)sc[j + 3] * AGG_D4, pol);
                a0.x += v0.x + v1.x; a0.y += v0.y + v1.y;
                a0.z += v0.z + v1.z; a0.w += v0.w + v1.w;
                a1.x += v2.x + v3.x; a1.y += v2.y + v3.y;
                a1.z += v2.z + v3.z; a1.w += v2.w + v3.w;
            }
            for (; j < L; ++j) {
                float4 v = ldg_el(e + (size_t)sc[j] * AGG_D4, pol);
                a0.x += v.x; a0.y += v.y; a0.z += v.z; a0.w += v.w;
            }
        }

        // ---- duplicate detection AFTER the gather (all lanes participate) ----
        unsigned p0m = __match_any_sync(0xffffffffu, c0);
        bool d0 = (lane < L) && ((p0m & lt) != 0);
        bool d1 = false, d2 = false;
        if (L > 32) {
            unsigned p1m = __match_any_sync(0xffffffffu, c1);
            d1 = (j1 < L) && ((p1m & lt) != 0);
            if (!d1 && j1 < L) {
                for (int i = 0; i < 32; ++i)
                    if (sc[i] == c1) { d1 = true; break; }
            }
            if (L > 64) {
                unsigned p2m = __match_any_sync(0xffffffffu, c2);
                d2 = (j2 < L) && ((p2m & lt) != 0);
                if (!d2 && j2 < L) {
                    for (int i = 0; i < 64; ++i)
                        if (sc[i] == c2) { d2 = true; break; }
                }
            }
        }
        const unsigned m0 = __ballot_sync(0xffffffffu, d0);
        const unsigned m1 = __ballot_sync(0xffffffffu, d1);
        const unsigned m2 = __ballot_sync(0xffffffffu, d2);
        Lu = L - (__popc(m0) + __popc(m1) + __popc(m2));

        // ---- subtract duplicate occurrences (almost always all-zero masks) ----
        if (act && (m0 | m1 | m2)) {
            unsigned masks[3] = { m0, m1, m2 };
            #pragma unroll
            for (int k = 0; k < 3; ++k) {
                unsigned m = masks[k];
                while (m) {
                    int b = __ffs(m) - 1; m &= m - 1;
                    float4 v = ldg_el(e + (size_t)sc[k * 32 + b] * AGG_D4, pol);
                    a0.x -= v.x; a0.y -= v.y; a0.z -= v.z; a0.w -= v.w;
                }
            }
        }
    } else {
        // Unreachable-for-this-data fallback: O(L^2) global dedup, direct accumulate.
        for (int j = 0; j < L; ++j) {
            int c = col_idx[start + j];
            bool valid = true;
            for (int i = 0; i < j; ++i)
                if (col_idx[start + i] == c) { valid = false; break; }
            if (!valid) continue;
            ++Lu;
            if (act) {
                float4 v = ldg_el(e + (size_t)c * AGG_D4, pol);
                a0.x += v.x; a0.y += v.y; a0.z += v.z; a0.w += v.w;
            }
        }
    }

    if (act) {
        const float inv = 1.0f / fmaxf((float)Lu, 1e-8f);
        float4 t;
        t.x = (a0.x + a1.x) * inv;
        t.y = (a0.y + a1.y) * inv;
        t.z = (a0.z + a1.z) * inv;
        t.w = (a0.w + a1.w) * inv;
        __stcs(&out4[(size_t)r * AGG_D4 + d4], t);   // stream output past L2
    }
}

extern "C" void kernel_launch(void* const* d_in, const int* in_sizes, int n_in,
                              void* d_out, int out_size) {
    const int*   row_idx = (const int*)  d_in[0];
    const int*   col_idx = (const int*)  d_in[1];
    const float* embed   = (const float*)d_in[2];
    float*       out     = (float*)      d_out;

    const int E = in_sizes[0];
    const int B = out_size / 300;

    const int k1_threads = E / 4 + 1;
    build_row_starts<<<(k1_threads + 255) / 256, 256>>>(row_idx, E, B);
    const int total_warps = 3 * B;
    mean_agg_kernel<<<(total_warps + WARPS_PB - 1) / WARPS_PB, WARPS_PB * 32>>>(
        col_idx, (const float4*)embed, (float4*)out, B);
}

// round 15
// speedup vs baseline: 1.4015x; 1.0122x over previous
#include <cuda_runtime.h>
#include <cuda_bf16.h>

// MeanAggregator: out[r,:] = mean over UNIQUE neighbors c of row r of embed[c,:]
// row_idx sorted ascending. D = 300 floats = 75 float4.
// R15 = R8 gather kernel EXACTLY (warp per (row,slot), GATHER-ALL + SUBTRACT-
// DUPLICATES, dup detect deferred, plain LDG.128 loads) + vectorized int4 CSR
// build from R14 (the only R14 piece that measured as a win).

#define AGG_D4   75
#define AGG_MAXL 96            // fast-path cap: 3 chunks (L ~ Poisson(32), max ~70)
#define AGG_MAXB 65536
#define WARPS_PB 8             // 256-thread blocks

__device__ int g_row_start[AGG_MAXB + 1];

// K1: CSR row pointers by diff-scatter, vectorized: each thread owns boundaries
// i in [4t, 4t+4). Fast path: one int4 load + shfl_up for row_idx[4t-1]
// (lane 0 patches with a scalar load). Edges fall back to the scalar logic.
__global__ void build_row_starts(const int* __restrict__ row_idx, int E, int B) {
    const int t    = blockIdx.x * blockDim.x + threadIdx.x;
    const int lane = threadIdx.x & 31;
    const int i0   = t * 4;
    if (i0 > E) return;

    if (i0 > 0 && i0 + 4 <= E) {
        int4 q = *reinterpret_cast<const int4*>(row_idx + i0);
        int prevv = __shfl_up_sync(0xffffffffu, q.w, 1);
        if (lane == 0) prevv = row_idx[i0 - 1];
        int vals[4] = { q.x, q.y, q.z, q.w };
        int p = prevv;
        #pragma unroll
        for (int k = 0; k < 4; ++k) {
            int cur = vals[k];
            for (int v = p + 1; v <= cur; ++v) g_row_start[v] = i0 + k;
            p = cur;
        }
    } else {
        // shfl source above may be inactive here; pure scalar edge handling
        #pragma unroll
        for (int k = 0; k < 4; ++k) {
            int i = i0 + k;
            if (i > E) break;
            if (i == 0) {
                int cur = row_idx[0];
                for (int v = 0; v <= cur; ++v) g_row_start[v] = 0;
            } else if (i == E) {
                int prev = row_idx[E - 1];
                for (int v = prev + 1; v <= B; ++v) g_row_start[v] = E;
            } else {
                int prev = row_idx[i - 1];
                int cur  = row_idx[i];
                for (int v = prev + 1; v <= cur; ++v) g_row_start[v] = i;
            }
        }
    }
}

__global__ __launch_bounds__(WARPS_PB * 32) void mean_agg_kernel(
    const int*    __restrict__ col_idx,
    const float4* __restrict__ embed4,   // [U, 75]
    float4*       __restrict__ out4,     // [B, 75]
    int B)
{
    const int w    = threadIdx.x >> 5;
    const int lane = threadIdx.x & 31;
    const int gw   = blockIdx.x * WARPS_PB + w;   // global warp id
    const int r    = gw / 3;                      // row
    const int slot = gw - r * 3;                  // LDG slot 0/1/2
    if (r >= B) return;                           // warp-uniform

    const int  d4  = slot * 32 + lane;            // my float4 index in [0,75)
    const bool act = (d4 < AGG_D4);               // slot 2: lanes 0..10 only

    const int start = g_row_start[r];
    const int L     = g_row_start[r + 1] - start;

    __shared__ int s_col[WARPS_PB][AGG_MAXL];
    int* sc = s_col[w];

    float4 acc = make_float4(0.f, 0.f, 0.f, 0.f);
    const unsigned lt = (1u << lane) - 1u;
    const float4* __restrict__ e = embed4 + d4;
    int Lu = 0;

    if (L <= AGG_MAXL) {
        // ---- 3 independent coalesced chunk loads of col indices ----
        const int j1 = 32 + lane, j2 = 64 + lane;
        int c0 = (lane < L) ? col_idx[start + lane] : -(lane + 1);
        int c1 = (j1   < L) ? col_idx[start + j1]   : -(lane + 1);
        int c2 = (j2   < L) ? col_idx[start + j2]   : -(lane + 1);
        sc[lane] = c0;
        if (j1 < L) sc[j1] = c1;
        if (j2 < L) sc[j2] = c2;
        __syncwarp();

        // ---- main gather over ALL L entries (dups included): unroll-8,
        //      8 independent LDG.128 in flight, 1 LDG per neighbor ----
        if (act) {
            int j = 0;
            for (; j + 8 <= L; j += 8) {
                float4 v0 = e[(size_t)sc[j]     * AGG_D4];
                float4 v1 = e[(size_t)sc[j + 1] * AGG_D4];
                float4 v2 = e[(size_t)sc[j + 2] * AGG_D4];
                float4 v3 = e[(size_t)sc[j + 3] * AGG_D4];
                float4 v4 = e[(size_t)sc[j + 4] * AGG_D4];
                float4 v5 = e[(size_t)sc[j + 5] * AGG_D4];
                float4 v6 = e[(size_t)sc[j + 6] * AGG_D4];
                float4 v7 = e[(size_t)sc[j + 7] * AGG_D4];
                acc.x += (v0.x + v1.x + v2.x + v3.x) + (v4.x + v5.x + v6.x + v7.x);
                acc.y += (v0.y + v1.y + v2.y + v3.y) + (v4.y + v5.y + v6.y + v7.y);
                acc.z += (v0.z + v1.z + v2.z + v3.z) + (v4.z + v5.z + v6.z + v7.z);
                acc.w += (v0.w + v1.w + v2.w + v3.w) + (v4.w + v5.w + v6.w + v7.w);
            }
            for (; j + 4 <= L; j += 4) {
                float4 v0 = e[(size_t)sc[j]     * AGG_D4];
                float4 v1 = e[(size_t)sc[j + 1] * AGG_D4];
                float4 v2 = e[(size_t)sc[j + 2] * AGG_D4];
                float4 v3 = e[(size_t)sc[j + 3] * AGG_D4];
                acc.x += v0.x + v1.x + v2.x + v3.x;
                acc.y += v0.y + v1.y + v2.y + v3.y;
                acc.z += v0.z + v1.z + v2.z + v3.z;
                acc.w += v0.w + v1.w + v2.w + v3.w;
            }
            for (; j < L; ++j) {
                float4 v = e[(size_t)sc[j] * AGG_D4];
                acc.x += v.x; acc.y += v.y; acc.z += v.z; acc.w += v.w;
            }
        }

        // ---- duplicate detection AFTER the gather (all lanes participate) ----
        unsigned p0m = __match_any_sync(0xffffffffu, c0);
        bool d0 = (lane < L) && ((p0m & lt) != 0);
        bool d1 = false, d2 = false;
        if (L > 32) {
            unsigned p1m = __match_any_sync(0xffffffffu, c1);
            d1 = (j1 < L) && ((p1m & lt) != 0);
            if (!d1 && j1 < L) {
                for (int i = 0; i < 32; ++i)
                    if (sc[i] == c1) { d1 = true; break; }
            }
            if (L > 64) {
                unsigned p2m = __match_any_sync(0xffffffffu, c2);
                d2 = (j2 < L) && ((p2m & lt) != 0);
                if (!d2 && j2 < L) {
                    for (int i = 0; i < 64; ++i)
                        if (sc[i] == c2) { d2 = true; break; }
                }
            }
        }
        const unsigned m0 = __ballot_sync(0xffffffffu, d0);
        const unsigned m1 = __ballot_sync(0xffffffffu, d1);
        const unsigned m2 = __ballot_sync(0xffffffffu, d2);
        Lu = L - (__popc(m0) + __popc(m1) + __popc(m2));

        // ---- subtract duplicate occurrences (almost always all-zero masks) ----
        if (act && (m0 | m1 | m2)) {
            unsigned masks[3] = { m0, m1, m2 };
            #pragma unroll
            for (int k = 0; k < 3; ++k) {
                unsigned m = masks[k];
                while (m) {
                    int b = __ffs(m) - 1; m &= m - 1;
                    float4 v = e[(size_t)sc[k * 32 + b] * AGG_D4];
                    acc.x -= v.x; acc.y -= v.y; acc.z -= v.z; acc.w -= v.w;
                }
            }
        }
    } else {
        // Unreachable-for-this-data fallback: O(L^2) global dedup, direct accumulate.
        for (int j = 0; j < L; ++j) {
            int c = col_idx[start + j];
            bool valid = true;
            for (int i = 0; i < j; ++i)
                if (col_idx[start + i] == c) { valid = false; break; }
            if (!valid) continue;
            ++Lu;
            if (act) {
                float4 v = e[(size_t)c * AGG_D4];
                acc.x += v.x; acc.y += v.y; acc.z += v.z; acc.w += v.w;
            }
        }
    }

    if (act) {
        const float inv = 1.0f / fmaxf((float)Lu, 1e-8f);
        float4 t;
        t.x = acc.x * inv; t.y = acc.y * inv; t.z = acc.z * inv; t.w = acc.w * inv;
        out4[(size_t)r * AGG_D4 + d4] = t;
    }
}

extern "C" void kernel_launch(void* const* d_in, const int* in_sizes, int n_in,
                              void* d_out, int out_size) {
    const int*   row_idx = (const int*)  d_in[0];
    const int*   col_idx = (const int*)  d_in[1];
    const float* embed   = (const float*)d_in[2];
    float*       out     = (float*)      d_out;

    const int E = in_sizes[0];
    const int B = out_size / 300;

    const int k1_threads = E / 4 + 1;
    build_row_starts<<<(k1_threads + 255) / 256, 256>>>(row_idx, E, B);
    const int total_warps = 3 * B;
    mean_agg_kernel<<<(total_warps + WARPS_PB - 1) / WARPS_PB, WARPS_PB * 32>>>(
        col_idx, (const float4*)embed, (float4*)out, B);
}